// round 14
// baseline (speedup 1.0000x reference)
#include <cuda_runtime.h>
#include <cuda_fp16.h>
#include <math.h>
#include <stdint.h>

#define B_ 4
#define S_ 2048
#define D_ 1024
#define H_ 16
#define HD_ 64
#define M_ (B_*S_)   // 8192

// fp16 scratch
__device__ __half g_qh[(size_t)B_*H_*S_*HD_];
__device__ __half g_kh[(size_t)B_*H_*S_*HD_];
__device__ __half g_vh[(size_t)B_*H_*S_*HD_];
__device__ __half g_xh[(size_t)M_*D_];
__device__ __half g_wvh[(size_t)M_*D_];
__device__ __half g_wt[(size_t)3*H_*HD_*D_];    // [z][h][n=64][k=1024]
__device__ __half g_woh[(size_t)D_*D_];         // [n][k]

// ---------------------------------------------------------------------------
__device__ __forceinline__ uint32_t smem_u32(const void* p) {
    uint32_t a;
    asm("{ .reg .u64 t; cvta.to.shared.u64 t, %1; cvt.u32.u64 %0, t; }" : "=r"(a) : "l"(p));
    return a;
}
__device__ __forceinline__ void cpa16(uint32_t dst, const void* src) {
    asm volatile("cp.async.cg.shared.global [%0], [%1], 16;" :: "r"(dst), "l"(src));
}
__device__ __forceinline__ void cpa_commit() {
    asm volatile("cp.async.commit_group;" ::: "memory");
}
__device__ __forceinline__ float ex2(float x) {
    float r; asm("ex2.approx.ftz.f32 %0, %1;" : "=f"(r) : "f"(x)); return r;
}
__device__ __forceinline__ void mma16816(float c[4], const uint32_t a[4], const uint32_t b[2]) {
    asm volatile("mma.sync.aligned.m16n8k16.row.col.f32.f16.f16.f32 "
                 "{%0,%1,%2,%3}, {%4,%5,%6,%7}, {%8,%9}, {%0,%1,%2,%3};"
                 : "+f"(c[0]), "+f"(c[1]), "+f"(c[2]), "+f"(c[3])
                 : "r"(a[0]), "r"(a[1]), "r"(a[2]), "r"(a[3]), "r"(b[0]), "r"(b[1]));
}

// =================== GEMM (frozen at R12/R13) ===============================
#define RS2 144
#define TILE2 (128 * RS2)          // 18432 B
#define STAGE2 (2 * TILE2)         // 36864 B (A+B)
#define GSMEM (3 * STAGE2)         // 110592 B
#define NKT2 16                    // 1024 / 64

__device__ __forceinline__ void load_stage(uint32_t sbase,
                                           const __half* __restrict__ A,
                                           const __half* __restrict__ Bg,
                                           int kt, int tid) {
    const uint32_t sA = sbase, sB = sbase + TILE2;
    #pragma unroll
    for (int i = 0; i < 4; ++i) {
        int idx = tid + i * 256;
        int row = idx >> 3, c = idx & 7;
        const size_t go = (size_t)row * D_ + kt * 64 + c * 8;
        cpa16(sA + row * RS2 + c * 16, A + go);
        cpa16(sB + row * RS2 + c * 16, Bg + go);
    }
}

__device__ __forceinline__ void load_frag_a(uint32_t sA, int ks, int warp_m, int lane,
                                            int i, uint32_t a[4]) {
    int row = warp_m * 64 + i * 16 + (lane & 15);
    uint32_t addr = sA + row * RS2 + (ks * 16 + (lane >> 4) * 8) * 2;
    asm volatile("ldmatrix.sync.aligned.m8n8.x4.shared.b16 {%0,%1,%2,%3}, [%4];"
                 : "=r"(a[0]), "=r"(a[1]), "=r"(a[2]), "=r"(a[3]) : "r"(addr));
}

__device__ __forceinline__ void load_frag_b(uint32_t sB, int ks, int warp_n, int lane,
                                            int jj, uint32_t b0[2], uint32_t b1[2]) {
    int g = lane >> 3, lr = lane & 7;
    int n = warp_n * 32 + jj * 16 + (g >> 1) * 8 + lr;
    uint32_t addr = sB + n * RS2 + (ks * 16 + (g & 1) * 8) * 2;
    uint32_t r0, r1, r2, r3;
    asm volatile("ldmatrix.sync.aligned.m8n8.x4.shared.b16 {%0,%1,%2,%3}, [%4];"
                 : "=r"(r0), "=r"(r1), "=r"(r2), "=r"(r3) : "r"(addr));
    b0[0] = r0; b0[1] = r1;
    b1[0] = r2; b1[1] = r3;
}

__device__ __forceinline__ void gemm_main(uint32_t s, const __half* __restrict__ A,
                                          const __half* __restrict__ Bg,
                                          int tid, int warp_m, int warp_n, int lane,
                                          float c[4][4][4]) {
    load_stage(s + 0 * STAGE2, A, Bg, 0, tid); cpa_commit();
    load_stage(s + 1 * STAGE2, A, Bg, 1, tid); cpa_commit();

    uint32_t af[2][4][4], bf[2][4][2];

    #pragma unroll 1
    for (int kt = 0; kt < NKT2; ++kt) {
        if (kt < NKT2 - 1) asm volatile("cp.async.wait_group 1;" ::: "memory");
        else               asm volatile("cp.async.wait_group 0;" ::: "memory");
        __syncthreads();
        const uint32_t sA = s + (kt % 3) * STAGE2, sB = sA + TILE2;

        #pragma unroll
        for (int i = 0; i < 4; ++i) load_frag_a(sA, 0, warp_m, lane, i, af[0][i]);
        load_frag_b(sB, 0, warp_n, lane, 0, bf[0][0], bf[0][1]);
        load_frag_b(sB, 0, warp_n, lane, 1, bf[0][2], bf[0][3]);

        if (kt + 2 < NKT2) {
            load_stage(s + ((kt + 2) % 3) * STAGE2, A, Bg, kt + 2, tid);
            cpa_commit();
        }

        #pragma unroll
        for (int ks = 0; ks < 4; ++ks) {
            const int cur = ks & 1, nxt = cur ^ 1;
            const bool pf = (ks < 3);
            #pragma unroll
            for (int j = 0; j < 4; ++j) mma16816(c[0][j], af[cur][0], bf[cur][j]);
            if (pf) {
                load_frag_a(sA, ks + 1, warp_m, lane, 0, af[nxt][0]);
                load_frag_a(sA, ks + 1, warp_m, lane, 1, af[nxt][1]);
            }
            #pragma unroll
            for (int j = 0; j < 4; ++j) mma16816(c[1][j], af[cur][1], bf[cur][j]);
            if (pf) {
                load_frag_a(sA, ks + 1, warp_m, lane, 2, af[nxt][2]);
                load_frag_a(sA, ks + 1, warp_m, lane, 3, af[nxt][3]);
            }
            #pragma unroll
            for (int j = 0; j < 4; ++j) mma16816(c[2][j], af[cur][2], bf[cur][j]);
            if (pf) {
                load_frag_b(sB, ks + 1, warp_n, lane, 0, bf[nxt][0], bf[nxt][1]);
                load_frag_b(sB, ks + 1, warp_n, lane, 1, bf[nxt][2], bf[nxt][3]);
            }
            #pragma unroll
            for (int j = 0; j < 4; ++j) mma16816(c[3][j], af[cur][3], bf[cur][j]);
        }
    }
}

// ---------------------------------------------------------------------------
// QKV projection -> fp16 Q/K/V
// ---------------------------------------------------------------------------
__global__ __launch_bounds__(256, 2) void qkv_mma(
    const __half* __restrict__ Xh, const __half* __restrict__ Wt,
    const float* __restrict__ bq, const float* __restrict__ bk,
    const float* __restrict__ bv) {
    extern __shared__ __align__(16) char sm[];
    const uint32_t s = smem_u32(sm);
    const int tid = threadIdx.x, lane = tid & 31, wid = tid >> 5;
    const int warp_m = wid & 1, warp_n = wid >> 1;
    const int z = blockIdx.z, h0 = blockIdx.x * 2, m0 = blockIdx.y * 128;

    const __half* A  = Xh + (size_t)m0 * D_;
    const __half* Bg = Wt + ((size_t)(z * H_ + h0) * HD_) * D_;
    const float* bias = (z == 0) ? bq : (z == 1) ? bk : bv;
    __half* out       = (z == 0) ? g_qh : (z == 1) ? g_kh : g_vh;

    float c[4][4][4] = {};
    gemm_main(s, A, Bg, tid, warp_m, warp_n, lane, c);

    #pragma unroll
    for (int i = 0; i < 4; ++i) {
        #pragma unroll
        for (int j = 0; j < 4; ++j) {
            const int n = warp_n * 32 + j * 8 + (lane & 3) * 2;
            const int head = h0 + (n >> 6), e = n & 63;
            const float b0 = bias[head * HD_ + e], b1 = bias[head * HD_ + e + 1];
            #pragma unroll
            for (int half_ = 0; half_ < 2; ++half_) {
                const int m = m0 + warp_m * 64 + i * 16 + (lane >> 2) + half_ * 8;
                const int bb = m >> 11, sI = m & 2047;
                __half2 hv = __floats2half2_rn(c[i][j][half_ * 2 + 0] + b0,
                                               c[i][j][half_ * 2 + 1] + b1);
                *(__half2*)(out + (((size_t)(bb * H_ + head) * S_ + sI) * HD_ + e)) = hv;
            }
        }
    }
}

// ---------------------------------------------------------------------------
// Output projection: C = WVh * Woh^T + bo
// ---------------------------------------------------------------------------
__global__ __launch_bounds__(256, 2) void out_mma(
    const __half* __restrict__ WVh, const __half* __restrict__ Woh,
    const float* __restrict__ bo, float* __restrict__ outp) {
    extern __shared__ __align__(16) char sm[];
    const uint32_t s = smem_u32(sm);
    const int tid = threadIdx.x, lane = tid & 31, wid = tid >> 5;
    const int warp_m = wid & 1, warp_n = wid >> 1;
    const int n0 = blockIdx.x * 128, m0 = blockIdx.y * 128;

    const __half* A  = WVh + (size_t)m0 * D_;
    const __half* Bg = Woh + (size_t)n0 * D_;

    float c[4][4][4] = {};
    gemm_main(s, A, Bg, tid, warp_m, warp_n, lane, c);

    #pragma unroll
    for (int i = 0; i < 4; ++i) {
        #pragma unroll
        for (int j = 0; j < 4; ++j) {
            const int n = n0 + warp_n * 32 + j * 8 + (lane & 3) * 2;
            const float b0 = bo[n], b1 = bo[n + 1];
            #pragma unroll
            for (int half_ = 0; half_ < 2; ++half_) {
                const int m = m0 + warp_m * 64 + i * 16 + (lane >> 2) + half_ * 8;
                float2 v;
                v.x = c[i][j][half_ * 2 + 0] + b0;
                v.y = c[i][j][half_ * 2 + 1] + b1;
                *(float2*)(outp + (size_t)m * D_ + n) = v;
            }
        }
    }
}

// ===== attention: q-tile 256 (512 thr, 16 warps), 128-key staging ===========
#define ARS 144
#define ATILE2 (128 * ARS)         // 18432 B (128 keys x 64 hd)
#define ASTG2 (2 * ATILE2)         // 36864 B (K+V)
#define ASMEM (3 * ASTG2)          // 110592 B

__global__ __launch_bounds__(512, 1) void attn_mma() {
    extern __shared__ __align__(16) char sm[];
    const uint32_t s = smem_u32(sm);
    const int tid = threadIdx.x, lane = tid & 31, w = tid >> 5;   // w: 0..15
    const int bh = blockIdx.y;
    const int q0 = (gridDim.x - 1 - blockIdx.x) * 256;   // heavy tiles first

    const __half* __restrict__ Qb = g_qh + (size_t)bh * S_ * HD_;
    const __half* __restrict__ Kb = g_kh + (size_t)bh * S_ * HD_;
    const __half* __restrict__ Vb = g_vh + (size_t)bh * S_ * HD_;

    const int r0 = q0 + w * 16 + (lane >> 2);
    const int cq = lane & 3;
    const float SC = 0.18033688f;                 // 0.125 * log2(e)
    uint32_t qf[4][4];
    {
        const __half2 sc2 = __floats2half2_rn(SC, SC);
        const __half2* Qr0 = (const __half2*)(Qb + (size_t)r0 * HD_);
        const __half2* Qr1 = (const __half2*)(Qb + (size_t)(r0 + 8) * HD_);
        #pragma unroll
        for (int t = 0; t < 4; ++t) {
            __half2 v0 = __hmul2(Qr0[t * 8 + cq], sc2);
            __half2 v1 = __hmul2(Qr1[t * 8 + cq], sc2);
            __half2 v2 = __hmul2(Qr0[t * 8 + 4 + cq], sc2);
            __half2 v3 = __hmul2(Qr1[t * 8 + 4 + cq], sc2);
            qf[t][0] = *(const uint32_t*)&v0;
            qf[t][1] = *(const uint32_t*)&v1;
            qf[t][2] = *(const uint32_t*)&v2;
            qf[t][3] = *(const uint32_t*)&v3;
        }
    }

    float o[8][4];
    #pragma unroll
    for (int j = 0; j < 8; ++j)
        #pragma unroll
        for (int x = 0; x < 4; ++x) o[j][x] = 0.f;
    float m0 = -INFINITY, m1 = -INFINITY, l0 = 0.f, l1 = 0.f;

    const int NT = (q0 + 256) / 128;              // 128-key tiles

    auto load_tile = [&](int kt, int stg) {
        const uint32_t base = s + stg * ASTG2;
        #pragma unroll
        for (int i = 0; i < 2; ++i) {
            int idx = tid + i * 512;              // 0..1023
            int row = idx >> 3, c = idx & 7;      // 128 rows x 8 chunks
            const size_t go = (size_t)(kt * 128 + row) * HD_ + c * 8;
            cpa16(base + row * ARS + c * 16, Kb + go);
            cpa16(base + ATILE2 + row * ARS + c * 16, Vb + go);
        }
    };

    load_tile(0, 0); cpa_commit();
    if (NT > 1) { load_tile(1, 1); cpa_commit(); }

    const int g = lane >> 3, lr = lane & 7;
    const uint32_t ONES2 = 0x3C003C00u;
    uint32_t onesb[2] = {ONES2, ONES2};

    #pragma unroll 1
    for (int kt = 0; kt < NT; ++kt) {
        if (kt < NT - 1) asm volatile("cp.async.wait_group 1;" ::: "memory");
        else             asm volatile("cp.async.wait_group 0;" ::: "memory");
        __syncthreads();
        if (kt + 2 < NT) { load_tile(kt + 2, (kt + 2) % 3); cpa_commit(); }

        const uint32_t sKbase = s + (kt % 3) * ASTG2;

        #pragma unroll 1
        for (int half64 = 0; half64 < 2; ++half64) {
            const int k0 = kt * 128 + half64 * 64;
            if (k0 > r0 + 8) break;               // fully masked for this warp's rows
            const uint32_t sK = sKbase + half64 * 64 * ARS;
            const uint32_t sV = sKbase + ATILE2 + half64 * 64 * ARS;

            // ---- S = (Q*sc) K^T ----
            float sa[8][4];
            #pragma unroll
            for (int j = 0; j < 8; ++j)
                #pragma unroll
                for (int x = 0; x < 4; ++x) sa[j][x] = 0.f;
            #pragma unroll
            for (int t = 0; t < 4; ++t) {
                uint32_t kb[8][2];
                #pragma unroll
                for (int jp = 0; jp < 4; ++jp) {
                    const int n = jp * 16 + (g >> 1) * 8 + lr;
                    uint32_t addr = sK + n * ARS + t * 32 + (g & 1) * 16;
                    uint32_t r0_, r1_, r2_, r3_;
                    asm volatile("ldmatrix.sync.aligned.m8n8.x4.shared.b16 {%0,%1,%2,%3}, [%4];"
                                 : "=r"(r0_), "=r"(r1_), "=r"(r2_), "=r"(r3_) : "r"(addr));
                    kb[jp * 2][0] = r0_; kb[jp * 2][1] = r1_;
                    kb[jp * 2 + 1][0] = r2_; kb[jp * 2 + 1][1] = r3_;
                }
                #pragma unroll
                for (int j = 0; j < 8; ++j)
                    mma16816(sa[j], qf[t], kb[j]);
            }

            // ---- mask + running-max ----
            const bool needmask = (k0 + 63 > r0);
            float tm0 = -INFINITY, tm1 = -INFINITY;
            #pragma unroll
            for (int j = 0; j < 8; ++j) {
                if (needmask) {
                    const int col = k0 + j * 8 + (lane & 3) * 2;
                    if (col > r0)         sa[j][0] = -INFINITY;
                    if (col + 1 > r0)     sa[j][1] = -INFINITY;
                    if (col > r0 + 8)     sa[j][2] = -INFINITY;
                    if (col + 1 > r0 + 8) sa[j][3] = -INFINITY;
                }
                tm0 = fmaxf(tm0, fmaxf(sa[j][0], sa[j][1]));
                tm1 = fmaxf(tm1, fmaxf(sa[j][2], sa[j][3]));
            }
            tm0 = fmaxf(tm0, __shfl_xor_sync(0xffffffffu, tm0, 1));
            tm0 = fmaxf(tm0, __shfl_xor_sync(0xffffffffu, tm0, 2));
            tm1 = fmaxf(tm1, __shfl_xor_sync(0xffffffffu, tm1, 1));
            tm1 = fmaxf(tm1, __shfl_xor_sync(0xffffffffu, tm1, 2));

            const float mn0 = fmaxf(m0, tm0), mn1 = fmaxf(m1, tm1);
            const float c0 = ex2(m0 - mn0), c1 = ex2(m1 - mn1);
            m0 = mn0; m1 = mn1;

            // ---- P = exp2(S - m) in fp16x2 ----
            uint32_t pa[4][4];
            #pragma unroll
            for (int j = 0; j < 8; ++j) {
                const float a0 = sa[j][0] - mn0, a1 = sa[j][1] - mn0;
                const float a2 = sa[j][2] - mn1, a3 = sa[j][3] - mn1;
                uint32_t h01, h23;
                asm("cvt.rn.f16x2.f32 %0, %1, %2;" : "=r"(h01) : "f"(a1), "f"(a0));
                asm("cvt.rn.f16x2.f32 %0, %1, %2;" : "=r"(h23) : "f"(a3), "f"(a2));
                asm("ex2.approx.f16x2 %0, %1;" : "=r"(h01) : "r"(h01));
                asm("ex2.approx.f16x2 %0, %1;" : "=r"(h23) : "r"(h23));
                const int t = j >> 1;
                if ((j & 1) == 0) { pa[t][0] = h01; pa[t][1] = h23; }
                else              { pa[t][2] = h01; pa[t][3] = h23; }
            }

            // ---- rescale O ----
            #pragma unroll
            for (int j = 0; j < 8; ++j) {
                o[j][0] *= c0; o[j][1] *= c0;
                o[j][2] *= c1; o[j][3] *= c1;
            }

            // ---- O += P V, row sums via MMA ----
            float ls[4] = {0.f, 0.f, 0.f, 0.f};
            #pragma unroll
            for (int t = 0; t < 4; ++t) {
                uint32_t vb[8][2];
                #pragma unroll
                for (int jp = 0; jp < 4; ++jp) {
                    const int row = t * 16 + (g & 1) * 8 + lr;
                    uint32_t addr = sV + row * ARS + jp * 32 + (g >> 1) * 16;
                    uint32_t r0_, r1_, r2_, r3_;
                    asm volatile("ldmatrix.sync.aligned.m8n8.x4.trans.shared.b16 {%0,%1,%2,%3}, [%4];"
                                 : "=r"(r0_), "=r"(r1_), "=r"(r2_), "=r"(r3_) : "r"(addr));
                    vb[jp * 2][0] = r0_; vb[jp * 2][1] = r1_;
                    vb[jp * 2 + 1][0] = r2_; vb[jp * 2 + 1][1] = r3_;
                }
                mma16816(ls, pa[t], onesb);
                #pragma unroll
                for (int j = 0; j < 8; ++j)
                    mma16816(o[j], pa[t], vb[j]);
            }

            l0 = l0 * c0 + ls[0];
            l1 = l1 * c1 + ls[2];
        }
    }

    // ---- epilogue ----
    const float i0 = 1.f / l0, i1 = 1.f / l1;
    const int b = bh >> 4, h = bh & 15;
    __half* out0 = g_wvh + ((size_t)(b * S_) + r0) * D_ + h * HD_ + (lane & 3) * 2;
    __half* out1 = g_wvh + ((size_t)(b * S_) + r0 + 8) * D_ + h * HD_ + (lane & 3) * 2;
    #pragma unroll
    for (int j = 0; j < 8; ++j) {
        *(__half2*)(out0 + j * 8) = __floats2half2_rn(o[j][0] * i0, o[j][1] * i0);
        *(__half2*)(out1 + j * 8) = __floats2half2_rn(o[j][2] * i1, o[j][3] * i1);
    }
}

// ---------------------------------------------------------------------------
// fused prep (R13 layout)
// ---------------------------------------------------------------------------
#define NB_X  4096
#define NB_WO 512
#define NB_WT 3072

__global__ __launch_bounds__(512) void prep(
    const float* __restrict__ X,  const float* __restrict__ Wo,
    const float* __restrict__ Wq, const float* __restrict__ Wk,
    const float* __restrict__ Wv) {
    __shared__ float t[32][33];
    const int b = blockIdx.x, tid = threadIdx.x;

    if (b < NB_X) {
        const int i = (b * 512 + tid) * 4;
        float4 v = *(const float4*)(X + i);
        __half2* o = (__half2*)(g_xh + i);
        o[0] = __floats2half2_rn(v.x, v.y);
        o[1] = __floats2half2_rn(v.z, v.w);
    } else if (b < NB_X + NB_WO) {
        const int i = ((b - NB_X) * 512 + tid) * 4;
        float4 v = *(const float4*)(Wo + i);
        __half2* o = (__half2*)(g_woh + i);
        o[0] = __floats2half2_rn(v.x, v.y);
        o[1] = __floats2half2_rn(v.z, v.w);
    } else {
        if (tid >= 256) return;
        const int id = b - NB_X - NB_WO;
        const int bx = id & 1, by = (id >> 1) & 31, bz = id >> 6;
        const int z = bz >> 4, h = bz & 15;
        const float* W = ((z == 0) ? Wq : (z == 1) ? Wk : Wv) + (size_t)h * D_ * HD_;
        __half* out = g_wt + (size_t)bz * HD_ * D_;
        const int n0 = bx * 32, k0 = by * 32;
        const int tx = tid & 31, ty = tid >> 5;
        #pragma unroll
        for (int i = 0; i < 32; i += 8)
            t[ty + i][tx] = W[(size_t)(k0 + ty + i) * HD_ + n0 + tx];
        __syncthreads();
        #pragma unroll
        for (int i = 0; i < 32; i += 8)
            out[(size_t)(n0 + ty + i) * D_ + k0 + tx] = __float2half_rn(t[tx][ty + i]);
    }
}

// ---------------------------------------------------------------------------
extern "C" void kernel_launch(void* const* d_in, const int* in_sizes, int n_in,
                              void* d_out, int out_size) {
    const float* X  = (const float*)d_in[0];
    const float* Wq = (const float*)d_in[1];
    const float* bq = (const float*)d_in[2];
    const float* Wk = (const float*)d_in[3];
    const float* bk = (const float*)d_in[4];
    const float* Wv = (const float*)d_in[5];
    const float* bv = (const float*)d_in[6];
    const float* Wo = (const float*)d_in[7];
    const float* bo = (const float*)d_in[8];
    float* out = (float*)d_out;

    cudaFuncSetAttribute(qkv_mma, cudaFuncAttributeMaxDynamicSharedMemorySize, GSMEM);
    cudaFuncSetAttribute(out_mma, cudaFuncAttributeMaxDynamicSharedMemorySize, GSMEM);
    cudaFuncSetAttribute(attn_mma, cudaFuncAttributeMaxDynamicSharedMemorySize, ASMEM);

    __half* xh  = nullptr; cudaGetSymbolAddress((void**)&xh,  g_xh);
    __half* wvh = nullptr; cudaGetSymbolAddress((void**)&wvh, g_wvh);
    __half* wt  = nullptr; cudaGetSymbolAddress((void**)&wt,  g_wt);
    __half* woh = nullptr; cudaGetSymbolAddress((void**)&woh, g_woh);

    prep<<<NB_X + NB_WO + NB_WT, 512>>>(X, Wo, Wq, Wk, Wv);
    qkv_mma<<<dim3(H_ / 2, M_ / 128, 3), 256, GSMEM>>>(xh, wt, bq, bk, bv);
    attn_mma<<<dim3(S_ / 256, B_ * H_), 512, ASMEM>>>();
    out_mma<<<dim3(D_ / 128, M_ / 128), 256, GSMEM>>>(wvh, woh, bo, out);
}

// round 15
// speedup vs baseline: 1.0169x; 1.0169x over previous
#include <cuda_runtime.h>
#include <cuda_fp16.h>
#include <math.h>
#include <stdint.h>

#define B_ 4
#define S_ 2048
#define D_ 1024
#define H_ 16
#define HD_ 64
#define M_ (B_*S_)   // 8192

// fp16 scratch
__device__ __half g_qh[(size_t)B_*H_*S_*HD_];
__device__ __half g_kh[(size_t)B_*H_*S_*HD_];
__device__ __half g_vh[(size_t)B_*H_*S_*HD_];
__device__ __half g_xh[(size_t)M_*D_];
__device__ __half g_wvh[(size_t)M_*D_];
__device__ __half g_wt[(size_t)3*H_*HD_*D_];    // [z][h][n=64][k=1024]
__device__ __half g_woh[(size_t)D_*D_];         // [n][k]

// ---------------------------------------------------------------------------
__device__ __forceinline__ uint32_t smem_u32(const void* p) {
    uint32_t a;
    asm("{ .reg .u64 t; cvta.to.shared.u64 t, %1; cvt.u32.u64 %0, t; }" : "=r"(a) : "l"(p));
    return a;
}
__device__ __forceinline__ void cpa16(uint32_t dst, const void* src) {
    asm volatile("cp.async.cg.shared.global [%0], [%1], 16;" :: "r"(dst), "l"(src));
}
__device__ __forceinline__ void cpa_commit() {
    asm volatile("cp.async.commit_group;" ::: "memory");
}
__device__ __forceinline__ float ex2(float x) {
    float r; asm("ex2.approx.ftz.f32 %0, %1;" : "=f"(r) : "f"(x)); return r;
}
__device__ __forceinline__ void mma16816(float c[4], const uint32_t a[4], const uint32_t b[2]) {
    asm volatile("mma.sync.aligned.m16n8k16.row.col.f32.f16.f16.f32 "
                 "{%0,%1,%2,%3}, {%4,%5,%6,%7}, {%8,%9}, {%0,%1,%2,%3};"
                 : "+f"(c[0]), "+f"(c[1]), "+f"(c[2]), "+f"(c[3])
                 : "r"(a[0]), "r"(a[1]), "r"(a[2]), "r"(a[3]), "r"(b[0]), "r"(b[1]));
}

// =================== GEMM (frozen at R12/R13) ===============================
#define RS2 144
#define TILE2 (128 * RS2)          // 18432 B
#define STAGE2 (2 * TILE2)         // 36864 B (A+B)
#define GSMEM (3 * STAGE2)         // 110592 B
#define NKT2 16                    // 1024 / 64

__device__ __forceinline__ void load_stage(uint32_t sbase,
                                           const __half* __restrict__ A,
                                           const __half* __restrict__ Bg,
                                           int kt, int tid) {
    const uint32_t sA = sbase, sB = sbase + TILE2;
    #pragma unroll
    for (int i = 0; i < 4; ++i) {
        int idx = tid + i * 256;
        int row = idx >> 3, c = idx & 7;
        const size_t go = (size_t)row * D_ + kt * 64 + c * 8;
        cpa16(sA + row * RS2 + c * 16, A + go);
        cpa16(sB + row * RS2 + c * 16, Bg + go);
    }
}

__device__ __forceinline__ void load_frag_a(uint32_t sA, int ks, int warp_m, int lane,
                                            int i, uint32_t a[4]) {
    int row = warp_m * 64 + i * 16 + (lane & 15);
    uint32_t addr = sA + row * RS2 + (ks * 16 + (lane >> 4) * 8) * 2;
    asm volatile("ldmatrix.sync.aligned.m8n8.x4.shared.b16 {%0,%1,%2,%3}, [%4];"
                 : "=r"(a[0]), "=r"(a[1]), "=r"(a[2]), "=r"(a[3]) : "r"(addr));
}

__device__ __forceinline__ void load_frag_b(uint32_t sB, int ks, int warp_n, int lane,
                                            int jj, uint32_t b0[2], uint32_t b1[2]) {
    int g = lane >> 3, lr = lane & 7;
    int n = warp_n * 32 + jj * 16 + (g >> 1) * 8 + lr;
    uint32_t addr = sB + n * RS2 + (ks * 16 + (g & 1) * 8) * 2;
    uint32_t r0, r1, r2, r3;
    asm volatile("ldmatrix.sync.aligned.m8n8.x4.shared.b16 {%0,%1,%2,%3}, [%4];"
                 : "=r"(r0), "=r"(r1), "=r"(r2), "=r"(r3) : "r"(addr));
    b0[0] = r0; b0[1] = r1;
    b1[0] = r2; b1[1] = r3;
}

__device__ __forceinline__ void gemm_main(uint32_t s, const __half* __restrict__ A,
                                          const __half* __restrict__ Bg,
                                          int tid, int warp_m, int warp_n, int lane,
                                          float c[4][4][4]) {
    load_stage(s + 0 * STAGE2, A, Bg, 0, tid); cpa_commit();
    load_stage(s + 1 * STAGE2, A, Bg, 1, tid); cpa_commit();

    uint32_t af[2][4][4], bf[2][4][2];

    #pragma unroll 1
    for (int kt = 0; kt < NKT2; ++kt) {
        if (kt < NKT2 - 1) asm volatile("cp.async.wait_group 1;" ::: "memory");
        else               asm volatile("cp.async.wait_group 0;" ::: "memory");
        __syncthreads();
        const uint32_t sA = s + (kt % 3) * STAGE2, sB = sA + TILE2;

        #pragma unroll
        for (int i = 0; i < 4; ++i) load_frag_a(sA, 0, warp_m, lane, i, af[0][i]);
        load_frag_b(sB, 0, warp_n, lane, 0, bf[0][0], bf[0][1]);
        load_frag_b(sB, 0, warp_n, lane, 1, bf[0][2], bf[0][3]);

        if (kt + 2 < NKT2) {
            load_stage(s + ((kt + 2) % 3) * STAGE2, A, Bg, kt + 2, tid);
            cpa_commit();
        }

        #pragma unroll
        for (int ks = 0; ks < 4; ++ks) {
            const int cur = ks & 1, nxt = cur ^ 1;
            const bool pf = (ks < 3);
            #pragma unroll
            for (int j = 0; j < 4; ++j) mma16816(c[0][j], af[cur][0], bf[cur][j]);
            if (pf) {
                load_frag_a(sA, ks + 1, warp_m, lane, 0, af[nxt][0]);
                load_frag_a(sA, ks + 1, warp_m, lane, 1, af[nxt][1]);
            }
            #pragma unroll
            for (int j = 0; j < 4; ++j) mma16816(c[1][j], af[cur][1], bf[cur][j]);
            if (pf) {
                load_frag_a(sA, ks + 1, warp_m, lane, 2, af[nxt][2]);
                load_frag_a(sA, ks + 1, warp_m, lane, 3, af[nxt][3]);
            }
            #pragma unroll
            for (int j = 0; j < 4; ++j) mma16816(c[2][j], af[cur][2], bf[cur][j]);
            if (pf) {
                load_frag_b(sB, ks + 1, warp_n, lane, 0, bf[nxt][0], bf[nxt][1]);
                load_frag_b(sB, ks + 1, warp_n, lane, 1, bf[nxt][2], bf[nxt][3]);
            }
            #pragma unroll
            for (int j = 0; j < 4; ++j) mma16816(c[3][j], af[cur][3], bf[cur][j]);
        }
    }
}

// ---------------------------------------------------------------------------
// QKV projection -> fp16 Q/K/V
// ---------------------------------------------------------------------------
__global__ __launch_bounds__(256, 2) void qkv_mma(
    const __half* __restrict__ Xh, const __half* __restrict__ Wt,
    const float* __restrict__ bq, const float* __restrict__ bk,
    const float* __restrict__ bv) {
    extern __shared__ __align__(16) char sm[];
    const uint32_t s = smem_u32(sm);
    const int tid = threadIdx.x, lane = tid & 31, wid = tid >> 5;
    const int warp_m = wid & 1, warp_n = wid >> 1;
    const int z = blockIdx.z, h0 = blockIdx.x * 2, m0 = blockIdx.y * 128;

    const __half* A  = Xh + (size_t)m0 * D_;
    const __half* Bg = Wt + ((size_t)(z * H_ + h0) * HD_) * D_;
    const float* bias = (z == 0) ? bq : (z == 1) ? bk : bv;
    __half* out       = (z == 0) ? g_qh : (z == 1) ? g_kh : g_vh;

    float c[4][4][4] = {};
    gemm_main(s, A, Bg, tid, warp_m, warp_n, lane, c);

    #pragma unroll
    for (int i = 0; i < 4; ++i) {
        #pragma unroll
        for (int j = 0; j < 4; ++j) {
            const int n = warp_n * 32 + j * 8 + (lane & 3) * 2;
            const int head = h0 + (n >> 6), e = n & 63;
            const float b0 = bias[head * HD_ + e], b1 = bias[head * HD_ + e + 1];
            #pragma unroll
            for (int half_ = 0; half_ < 2; ++half_) {
                const int m = m0 + warp_m * 64 + i * 16 + (lane >> 2) + half_ * 8;
                const int bb = m >> 11, sI = m & 2047;
                __half2 hv = __floats2half2_rn(c[i][j][half_ * 2 + 0] + b0,
                                               c[i][j][half_ * 2 + 1] + b1);
                *(__half2*)(out + (((size_t)(bb * H_ + head) * S_ + sI) * HD_ + e)) = hv;
            }
        }
    }
}

// ---------------------------------------------------------------------------
// Output projection: C = WVh * Woh^T + bo
// ---------------------------------------------------------------------------
__global__ __launch_bounds__(256, 2) void out_mma(
    const __half* __restrict__ WVh, const __half* __restrict__ Woh,
    const float* __restrict__ bo, float* __restrict__ outp) {
    extern __shared__ __align__(16) char sm[];
    const uint32_t s = smem_u32(sm);
    const int tid = threadIdx.x, lane = tid & 31, wid = tid >> 5;
    const int warp_m = wid & 1, warp_n = wid >> 1;
    const int n0 = blockIdx.x * 128, m0 = blockIdx.y * 128;

    const __half* A  = WVh + (size_t)m0 * D_;
    const __half* Bg = Woh + (size_t)n0 * D_;

    float c[4][4][4] = {};
    gemm_main(s, A, Bg, tid, warp_m, warp_n, lane, c);

    #pragma unroll
    for (int i = 0; i < 4; ++i) {
        #pragma unroll
        for (int j = 0; j < 4; ++j) {
            const int n = n0 + warp_n * 32 + j * 8 + (lane & 3) * 2;
            const float b0 = bo[n], b1 = bo[n + 1];
            #pragma unroll
            for (int half_ = 0; half_ < 2; ++half_) {
                const int m = m0 + warp_m * 64 + i * 16 + (lane >> 2) + half_ * 8;
                float2 v;
                v.x = c[i][j][half_ * 2 + 0] + b0;
                v.y = c[i][j][half_ * 2 + 1] + b1;
                *(float2*)(outp + (size_t)m * D_ + n) = v;
            }
        }
    }
}

// ===== attention: R13 (q-tile 128, 128-key staging) + diagonal-chunk skip ====
#define ARS 144
#define ATILE2 (128 * ARS)         // 18432 B (128 keys x 64 hd)
#define ASTG2 (2 * ATILE2)         // 36864 B (K+V)
#define ASMEM (3 * ASTG2)          // 110592 B

__global__ __launch_bounds__(256, 2) void attn_mma() {
    extern __shared__ __align__(16) char sm[];
    const uint32_t s = smem_u32(sm);
    const int tid = threadIdx.x, lane = tid & 31, w = tid >> 5;
    const int bh = blockIdx.y;
    const int q0 = (gridDim.x - 1 - blockIdx.x) * 128;   // heavy tiles first

    const __half* __restrict__ Qb = g_qh + (size_t)bh * S_ * HD_;
    const __half* __restrict__ Kb = g_kh + (size_t)bh * S_ * HD_;
    const __half* __restrict__ Vb = g_vh + (size_t)bh * S_ * HD_;

    const int r0 = q0 + w * 16 + (lane >> 2);
    const int cq = lane & 3;
    const float SC = 0.18033688f;                 // 0.125 * log2(e)
    uint32_t qf[4][4];
    {
        const __half2 sc2 = __floats2half2_rn(SC, SC);
        const __half2* Qr0 = (const __half2*)(Qb + (size_t)r0 * HD_);
        const __half2* Qr1 = (const __half2*)(Qb + (size_t)(r0 + 8) * HD_);
        #pragma unroll
        for (int t = 0; t < 4; ++t) {
            __half2 v0 = __hmul2(Qr0[t * 8 + cq], sc2);
            __half2 v1 = __hmul2(Qr1[t * 8 + cq], sc2);
            __half2 v2 = __hmul2(Qr0[t * 8 + 4 + cq], sc2);
            __half2 v3 = __hmul2(Qr1[t * 8 + 4 + cq], sc2);
            qf[t][0] = *(const uint32_t*)&v0;
            qf[t][1] = *(const uint32_t*)&v1;
            qf[t][2] = *(const uint32_t*)&v2;
            qf[t][3] = *(const uint32_t*)&v3;
        }
    }

    float o[8][4];
    #pragma unroll
    for (int j = 0; j < 8; ++j)
        #pragma unroll
        for (int x = 0; x < 4; ++x) o[j][x] = 0.f;
    float m0 = -INFINITY, m1 = -INFINITY, l0 = 0.f, l1 = 0.f;

    const int NT = (q0 + 128) / 128;              // 128-key tiles

    auto load_tile = [&](int kt, int stg) {
        const uint32_t base = s + stg * ASTG2;
        #pragma unroll
        for (int i = 0; i < 4; ++i) {
            int idx = tid + i * 256;              // 0..1023
            int row = idx >> 3, c = idx & 7;      // 128 rows x 8 chunks
            const size_t go = (size_t)(kt * 128 + row) * HD_ + c * 8;
            cpa16(base + row * ARS + c * 16, Kb + go);
            cpa16(base + ATILE2 + row * ARS + c * 16, Vb + go);
        }
    };

    load_tile(0, 0); cpa_commit();
    if (NT > 1) { load_tile(1, 1); cpa_commit(); }

    const int g = lane >> 3, lr = lane & 7;
    const uint32_t ONES2 = 0x3C003C00u;
    uint32_t onesb[2] = {ONES2, ONES2};

    #pragma unroll 1
    for (int kt = 0; kt < NT; ++kt) {
        if (kt < NT - 1) asm volatile("cp.async.wait_group 1;" ::: "memory");
        else             asm volatile("cp.async.wait_group 0;" ::: "memory");
        __syncthreads();
        if (kt + 2 < NT) { load_tile(kt + 2, (kt + 2) % 3); cpa_commit(); }

        const uint32_t sKbase = s + (kt % 3) * ASTG2;

        #pragma unroll 1
        for (int half64 = 0; half64 < 2; ++half64) {
            const int k0 = kt * 128 + half64 * 64;
            // warp-uniform skip of fully-masked chunks (k0-q0-w*16 ≡ 0 mod 16,
            // so no k0 falls inside the lane spread (r0+8 .. r0+15])
            if (k0 > r0 + 8) break;
            const uint32_t sK = sKbase + half64 * 64 * ARS;
            const uint32_t sV = sKbase + ATILE2 + half64 * 64 * ARS;

            // ---- S = (Q*sc) K^T ----
            float sa[8][4];
            #pragma unroll
            for (int j = 0; j < 8; ++j)
                #pragma unroll
                for (int x = 0; x < 4; ++x) sa[j][x] = 0.f;
            #pragma unroll
            for (int t = 0; t < 4; ++t) {
                uint32_t kb[8][2];
                #pragma unroll
                for (int jp = 0; jp < 4; ++jp) {
                    const int n = jp * 16 + (g >> 1) * 8 + lr;
                    uint32_t addr = sK + n * ARS + t * 32 + (g & 1) * 16;
                    uint32_t r0_, r1_, r2_, r3_;
                    asm volatile("ldmatrix.sync.aligned.m8n8.x4.shared.b16 {%0,%1,%2,%3}, [%4];"
                                 : "=r"(r0_), "=r"(r1_), "=r"(r2_), "=r"(r3_) : "r"(addr));
                    kb[jp * 2][0] = r0_; kb[jp * 2][1] = r1_;
                    kb[jp * 2 + 1][0] = r2_; kb[jp * 2 + 1][1] = r3_;
                }
                #pragma unroll
                for (int j = 0; j < 8; ++j)
                    mma16816(sa[j], qf[t], kb[j]);
            }

            // ---- mask + running-max ----
            const bool needmask = (k0 + 63 > r0);
            float tm0 = -INFINITY, tm1 = -INFINITY;
            #pragma unroll
            for (int j = 0; j < 8; ++j) {
                if (needmask) {
                    const int col = k0 + j * 8 + (lane & 3) * 2;
                    if (col > r0)         sa[j][0] = -INFINITY;
                    if (col + 1 > r0)     sa[j][1] = -INFINITY;
                    if (col > r0 + 8)     sa[j][2] = -INFINITY;
                    if (col + 1 > r0 + 8) sa[j][3] = -INFINITY;
                }
                tm0 = fmaxf(tm0, fmaxf(sa[j][0], sa[j][1]));
                tm1 = fmaxf(tm1, fmaxf(sa[j][2], sa[j][3]));
            }
            tm0 = fmaxf(tm0, __shfl_xor_sync(0xffffffffu, tm0, 1));
            tm0 = fmaxf(tm0, __shfl_xor_sync(0xffffffffu, tm0, 2));
            tm1 = fmaxf(tm1, __shfl_xor_sync(0xffffffffu, tm1, 1));
            tm1 = fmaxf(tm1, __shfl_xor_sync(0xffffffffu, tm1, 2));

            const float mn0 = fmaxf(m0, tm0), mn1 = fmaxf(m1, tm1);
            const float c0 = ex2(m0 - mn0), c1 = ex2(m1 - mn1);
            m0 = mn0; m1 = mn1;

            // ---- P = exp2(S - m) in fp16x2 ----
            uint32_t pa[4][4];
            #pragma unroll
            for (int j = 0; j < 8; ++j) {
                const float a0 = sa[j][0] - mn0, a1 = sa[j][1] - mn0;
                const float a2 = sa[j][2] - mn1, a3 = sa[j][3] - mn1;
                uint32_t h01, h23;
                asm("cvt.rn.f16x2.f32 %0, %1, %2;" : "=r"(h01) : "f"(a1), "f"(a0));
                asm("cvt.rn.f16x2.f32 %0, %1, %2;" : "=r"(h23) : "f"(a3), "f"(a2));
                asm("ex2.approx.f16x2 %0, %1;" : "=r"(h01) : "r"(h01));
                asm("ex2.approx.f16x2 %0, %1;" : "=r"(h23) : "r"(h23));
                const int t = j >> 1;
                if ((j & 1) == 0) { pa[t][0] = h01; pa[t][1] = h23; }
                else              { pa[t][2] = h01; pa[t][3] = h23; }
            }

            // ---- rescale O ----
            #pragma unroll
            for (int j = 0; j < 8; ++j) {
                o[j][0] *= c0; o[j][1] *= c0;
                o[j][2] *= c1; o[j][3] *= c1;
            }

            // ---- O += P V, row sums via MMA ----
            float ls[4] = {0.f, 0.f, 0.f, 0.f};
            #pragma unroll
            for (int t = 0; t < 4; ++t) {
                uint32_t vb[8][2];
                #pragma unroll
                for (int jp = 0; jp < 4; ++jp) {
                    const int row = t * 16 + (g & 1) * 8 + lr;
                    uint32_t addr = sV + row * ARS + jp * 32 + (g >> 1) * 16;
                    uint32_t r0_, r1_, r2_, r3_;
                    asm volatile("ldmatrix.sync.aligned.m8n8.x4.trans.shared.b16 {%0,%1,%2,%3}, [%4];"
                                 : "=r"(r0_), "=r"(r1_), "=r"(r2_), "=r"(r3_) : "r"(addr));
                    vb[jp * 2][0] = r0_; vb[jp * 2][1] = r1_;
                    vb[jp * 2 + 1][0] = r2_; vb[jp * 2 + 1][1] = r3_;
                }
                mma16816(ls, pa[t], onesb);
                #pragma unroll
                for (int j = 0; j < 8; ++j)
                    mma16816(o[j], pa[t], vb[j]);
            }

            l0 = l0 * c0 + ls[0];
            l1 = l1 * c1 + ls[2];
        }
    }

    // ---- epilogue ----
    const float i0 = 1.f / l0, i1 = 1.f / l1;
    const int b = bh >> 4, h = bh & 15;
    __half* out0 = g_wvh + ((size_t)(b * S_) + r0) * D_ + h * HD_ + (lane & 3) * 2;
    __half* out1 = g_wvh + ((size_t)(b * S_) + r0 + 8) * D_ + h * HD_ + (lane & 3) * 2;
    #pragma unroll
    for (int j = 0; j < 8; ++j) {
        *(__half2*)(out0 + j * 8) = __floats2half2_rn(o[j][0] * i0, o[j][1] * i0);
        *(__half2*)(out1 + j * 8) = __floats2half2_rn(o[j][2] * i1, o[j][3] * i1);
    }
}

// ---------------------------------------------------------------------------
// fused prep (R13 layout)
// ---------------------------------------------------------------------------
#define NB_X  4096
#define NB_WO 512
#define NB_WT 3072

__global__ __launch_bounds__(512) void prep(
    const float* __restrict__ X,  const float* __restrict__ Wo,
    const float* __restrict__ Wq, const float* __restrict__ Wk,
    const float* __restrict__ Wv) {
    __shared__ float t[32][33];
    const int b = blockIdx.x, tid = threadIdx.x;

    if (b < NB_X) {
        const int i = (b * 512 + tid) * 4;
        float4 v = *(const float4*)(X + i);
        __half2* o = (__half2*)(g_xh + i);
        o[0] = __floats2half2_rn(v.x, v.y);
        o[1] = __floats2half2_rn(v.z, v.w);
    } else if (b < NB_X + NB_WO) {
        const int i = ((b - NB_X) * 512 + tid) * 4;
        float4 v = *(const float4*)(Wo + i);
        __half2* o = (__half2*)(g_woh + i);
        o[0] = __floats2half2_rn(v.x, v.y);
        o[1] = __floats2half2_rn(v.z, v.w);
    } else {
        if (tid >= 256) return;
        const int id = b - NB_X - NB_WO;
        const int bx = id & 1, by = (id >> 1) & 31, bz = id >> 6;
        const int z = bz >> 4, h = bz & 15;
        const float* W = ((z == 0) ? Wq : (z == 1) ? Wk : Wv) + (size_t)h * D_ * HD_;
        __half* out = g_wt + (size_t)bz * HD_ * D_;
        const int n0 = bx * 32, k0 = by * 32;
        const int tx = tid & 31, ty = tid >> 5;
        #pragma unroll
        for (int i = 0; i < 32; i += 8)
            t[ty + i][tx] = W[(size_t)(k0 + ty + i) * HD_ + n0 + tx];
        __syncthreads();
        #pragma unroll
        for (int i = 0; i < 32; i += 8)
            out[(size_t)(n0 + ty + i) * D_ + k0 + tx] = __float2half_rn(t[tx][ty + i]);
    }
}

// ---------------------------------------------------------------------------
extern "C" void kernel_launch(void* const* d_in, const int* in_sizes, int n_in,
                              void* d_out, int out_size) {
    const float* X  = (const float*)d_in[0];
    const float* Wq = (const float*)d_in[1];
    const float* bq = (const float*)d_in[2];
    const float* Wk = (const float*)d_in[3];
    const float* bk = (const float*)d_in[4];
    const float* Wv = (const float*)d_in[5];
    const float* bv = (const float*)d_in[6];
    const float* Wo = (const float*)d_in[7];
    const float* bo = (const float*)d_in[8];
    float* out = (float*)d_out;

    cudaFuncSetAttribute(qkv_mma, cudaFuncAttributeMaxDynamicSharedMemorySize, GSMEM);
    cudaFuncSetAttribute(out_mma, cudaFuncAttributeMaxDynamicSharedMemorySize, GSMEM);
    cudaFuncSetAttribute(attn_mma, cudaFuncAttributeMaxDynamicSharedMemorySize, ASMEM);

    __half* xh  = nullptr; cudaGetSymbolAddress((void**)&xh,  g_xh);
    __half* wvh = nullptr; cudaGetSymbolAddress((void**)&wvh, g_wvh);
    __half* wt  = nullptr; cudaGetSymbolAddress((void**)&wt,  g_wt);
    __half* woh = nullptr; cudaGetSymbolAddress((void**)&woh, g_woh);

    prep<<<NB_X + NB_WO + NB_WT, 512>>>(X, Wo, Wq, Wk, Wv);
    qkv_mma<<<dim3(H_ / 2, M_ / 128, 3), 256, GSMEM>>>(xh, wt, bq, bk, bv);
    attn_mma<<<dim3(S_ / 128, B_ * H_), 256, ASMEM>>>();
    out_mma<<<dim3(D_ / 128, M_ / 128), 256, GSMEM>>>(wvh, woh, bo, out);
}

// round 16
// speedup vs baseline: 1.0943x; 1.0761x over previous
#include <cuda_runtime.h>
#include <cuda_fp16.h>
#include <math.h>
#include <stdint.h>

#define B_ 4
#define S_ 2048
#define D_ 1024
#define H_ 16
#define HD_ 64
#define M_ (B_*S_)   // 8192

// fp16 scratch
__device__ __half g_qh[(size_t)B_*H_*S_*HD_];
__device__ __half g_kh[(size_t)B_*H_*S_*HD_];
__device__ __half g_vh[(size_t)B_*H_*S_*HD_];
__device__ __half g_xh[(size_t)M_*D_];
__device__ __half g_wvh[(size_t)M_*D_];
__device__ __half g_wt[(size_t)3*H_*HD_*D_];    // [z][h][n=64][k=1024]
__device__ __half g_woh[(size_t)D_*D_];         // [n][k]

// ---------------------------------------------------------------------------
__device__ __forceinline__ uint32_t smem_u32(const void* p) {
    uint32_t a;
    asm("{ .reg .u64 t; cvta.to.shared.u64 t, %1; cvt.u32.u64 %0, t; }" : "=r"(a) : "l"(p));
    return a;
}
__device__ __forceinline__ void cpa16(uint32_t dst, const void* src) {
    asm volatile("cp.async.cg.shared.global [%0], [%1], 16;" :: "r"(dst), "l"(src));
}
__device__ __forceinline__ void cpa_commit() {
    asm volatile("cp.async.commit_group;" ::: "memory");
}
__device__ __forceinline__ float ex2(float x) {
    float r; asm("ex2.approx.ftz.f32 %0, %1;" : "=f"(r) : "f"(x)); return r;
}
__device__ __forceinline__ void mma16816(float c[4], const uint32_t a[4], const uint32_t b[2]) {
    asm volatile("mma.sync.aligned.m16n8k16.row.col.f32.f16.f16.f32 "
                 "{%0,%1,%2,%3}, {%4,%5,%6,%7}, {%8,%9}, {%0,%1,%2,%3};"
                 : "+f"(c[0]), "+f"(c[1]), "+f"(c[2]), "+f"(c[3])
                 : "r"(a[0]), "r"(a[1]), "r"(a[2]), "r"(a[3]), "r"(b[0]), "r"(b[1]));
}

// =================== GEMM (frozen at R12/R13) ===============================
#define RS2 144
#define TILE2 (128 * RS2)          // 18432 B
#define STAGE2 (2 * TILE2)         // 36864 B (A+B)
#define GSMEM (3 * STAGE2)         // 110592 B
#define NKT2 16                    // 1024 / 64

__device__ __forceinline__ void load_stage(uint32_t sbase,
                                           const __half* __restrict__ A,
                                           const __half* __restrict__ Bg,
                                           int kt, int tid) {
    const uint32_t sA = sbase, sB = sbase + TILE2;
    #pragma unroll
    for (int i = 0; i < 4; ++i) {
        int idx = tid + i * 256;
        int row = idx >> 3, c = idx & 7;
        const size_t go = (size_t)row * D_ + kt * 64 + c * 8;
        cpa16(sA + row * RS2 + c * 16, A + go);
        cpa16(sB + row * RS2 + c * 16, Bg + go);
    }
}

__device__ __forceinline__ void load_frag_a(uint32_t sA, int ks, int warp_m, int lane,
                                            int i, uint32_t a[4]) {
    int row = warp_m * 64 + i * 16 + (lane & 15);
    uint32_t addr = sA + row * RS2 + (ks * 16 + (lane >> 4) * 8) * 2;
    asm volatile("ldmatrix.sync.aligned.m8n8.x4.shared.b16 {%0,%1,%2,%3}, [%4];"
                 : "=r"(a[0]), "=r"(a[1]), "=r"(a[2]), "=r"(a[3]) : "r"(addr));
}

__device__ __forceinline__ void load_frag_b(uint32_t sB, int ks, int warp_n, int lane,
                                            int jj, uint32_t b0[2], uint32_t b1[2]) {
    int g = lane >> 3, lr = lane & 7;
    int n = warp_n * 32 + jj * 16 + (g >> 1) * 8 + lr;
    uint32_t addr = sB + n * RS2 + (ks * 16 + (g & 1) * 8) * 2;
    uint32_t r0, r1, r2, r3;
    asm volatile("ldmatrix.sync.aligned.m8n8.x4.shared.b16 {%0,%1,%2,%3}, [%4];"
                 : "=r"(r0), "=r"(r1), "=r"(r2), "=r"(r3) : "r"(addr));
    b0[0] = r0; b0[1] = r1;
    b1[0] = r2; b1[1] = r3;
}

__device__ __forceinline__ void gemm_main(uint32_t s, const __half* __restrict__ A,
                                          const __half* __restrict__ Bg,
                                          int tid, int warp_m, int warp_n, int lane,
                                          float c[4][4][4]) {
    load_stage(s + 0 * STAGE2, A, Bg, 0, tid); cpa_commit();
    load_stage(s + 1 * STAGE2, A, Bg, 1, tid); cpa_commit();

    uint32_t af[2][4][4], bf[2][4][2];

    #pragma unroll 1
    for (int kt = 0; kt < NKT2; ++kt) {
        if (kt < NKT2 - 1) asm volatile("cp.async.wait_group 1;" ::: "memory");
        else               asm volatile("cp.async.wait_group 0;" ::: "memory");
        __syncthreads();
        const uint32_t sA = s + (kt % 3) * STAGE2, sB = sA + TILE2;

        #pragma unroll
        for (int i = 0; i < 4; ++i) load_frag_a(sA, 0, warp_m, lane, i, af[0][i]);
        load_frag_b(sB, 0, warp_n, lane, 0, bf[0][0], bf[0][1]);
        load_frag_b(sB, 0, warp_n, lane, 1, bf[0][2], bf[0][3]);

        if (kt + 2 < NKT2) {
            load_stage(s + ((kt + 2) % 3) * STAGE2, A, Bg, kt + 2, tid);
            cpa_commit();
        }

        #pragma unroll
        for (int ks = 0; ks < 4; ++ks) {
            const int cur = ks & 1, nxt = cur ^ 1;
            const bool pf = (ks < 3);
            #pragma unroll
            for (int j = 0; j < 4; ++j) mma16816(c[0][j], af[cur][0], bf[cur][j]);
            if (pf) {
                load_frag_a(sA, ks + 1, warp_m, lane, 0, af[nxt][0]);
                load_frag_a(sA, ks + 1, warp_m, lane, 1, af[nxt][1]);
            }
            #pragma unroll
            for (int j = 0; j < 4; ++j) mma16816(c[1][j], af[cur][1], bf[cur][j]);
            if (pf) {
                load_frag_a(sA, ks + 1, warp_m, lane, 2, af[nxt][2]);
                load_frag_a(sA, ks + 1, warp_m, lane, 3, af[nxt][3]);
            }
            #pragma unroll
            for (int j = 0; j < 4; ++j) mma16816(c[2][j], af[cur][2], bf[cur][j]);
            if (pf) {
                load_frag_b(sB, ks + 1, warp_n, lane, 0, bf[nxt][0], bf[nxt][1]);
                load_frag_b(sB, ks + 1, warp_n, lane, 1, bf[nxt][2], bf[nxt][3]);
            }
            #pragma unroll
            for (int j = 0; j < 4; ++j) mma16816(c[3][j], af[cur][3], bf[cur][j]);
        }
    }
}

// ---------------------------------------------------------------------------
// QKV projection -> fp16 Q/K/V
// ---------------------------------------------------------------------------
__global__ __launch_bounds__(256, 2) void qkv_mma(
    const __half* __restrict__ Xh, const __half* __restrict__ Wt,
    const float* __restrict__ bq, const float* __restrict__ bk,
    const float* __restrict__ bv) {
    extern __shared__ __align__(16) char sm[];
    const uint32_t s = smem_u32(sm);
    const int tid = threadIdx.x, lane = tid & 31, wid = tid >> 5;
    const int warp_m = wid & 1, warp_n = wid >> 1;
    const int z = blockIdx.z, h0 = blockIdx.x * 2, m0 = blockIdx.y * 128;

    const __half* A  = Xh + (size_t)m0 * D_;
    const __half* Bg = Wt + ((size_t)(z * H_ + h0) * HD_) * D_;
    const float* bias = (z == 0) ? bq : (z == 1) ? bk : bv;
    __half* out       = (z == 0) ? g_qh : (z == 1) ? g_kh : g_vh;

    float c[4][4][4] = {};
    gemm_main(s, A, Bg, tid, warp_m, warp_n, lane, c);

    #pragma unroll
    for (int i = 0; i < 4; ++i) {
        #pragma unroll
        for (int j = 0; j < 4; ++j) {
            const int n = warp_n * 32 + j * 8 + (lane & 3) * 2;
            const int head = h0 + (n >> 6), e = n & 63;
            const float b0 = bias[head * HD_ + e], b1 = bias[head * HD_ + e + 1];
            #pragma unroll
            for (int half_ = 0; half_ < 2; ++half_) {
                const int m = m0 + warp_m * 64 + i * 16 + (lane >> 2) + half_ * 8;
                const int bb = m >> 11, sI = m & 2047;
                __half2 hv = __floats2half2_rn(c[i][j][half_ * 2 + 0] + b0,
                                               c[i][j][half_ * 2 + 1] + b1);
                *(__half2*)(out + (((size_t)(bb * H_ + head) * S_ + sI) * HD_ + e)) = hv;
            }
        }
    }
}

// ---------------------------------------------------------------------------
// Output projection half: m-tiles with s-tile index in [sbase, sbase+8)
// grid (8, 32): blockIdx.y -> (batch = y>>3, stile = (y&7)+sbase)
// ---------------------------------------------------------------------------
__global__ __launch_bounds__(256, 2) void out_mma(
    const __half* __restrict__ WVh, const __half* __restrict__ Woh,
    const float* __restrict__ bo, float* __restrict__ outp, int sbase) {
    extern __shared__ __align__(16) char sm[];
    const uint32_t s = smem_u32(sm);
    const int tid = threadIdx.x, lane = tid & 31, wid = tid >> 5;
    const int warp_m = wid & 1, warp_n = wid >> 1;
    const int n0 = blockIdx.x * 128;
    const int m0 = (((int)blockIdx.y >> 3) * 16 + ((int)blockIdx.y & 7) + sbase) * 128;

    const __half* A  = WVh + (size_t)m0 * D_;
    const __half* Bg = Woh + (size_t)n0 * D_;

    float c[4][4][4] = {};
    gemm_main(s, A, Bg, tid, warp_m, warp_n, lane, c);

    #pragma unroll
    for (int i = 0; i < 4; ++i) {
        #pragma unroll
        for (int j = 0; j < 4; ++j) {
            const int n = n0 + warp_n * 32 + j * 8 + (lane & 3) * 2;
            const float b0 = bo[n], b1 = bo[n + 1];
            #pragma unroll
            for (int half_ = 0; half_ < 2; ++half_) {
                const int m = m0 + warp_m * 64 + i * 16 + (lane >> 2) + half_ * 8;
                float2 v;
                v.x = c[i][j][half_ * 2 + 0] + b0;
                v.y = c[i][j][half_ * 2 + 1] + b1;
                *(float2*)(outp + (size_t)m * D_ + n) = v;
            }
        }
    }
}

// ===== attention half: q-tile index = tile_off - blockIdx.x (heavy first) ====
#define ARS 144
#define ATILE2 (128 * ARS)         // 18432 B (128 keys x 64 hd)
#define ASTG2 (2 * ATILE2)         // 36864 B (K+V)
#define ASMEM (3 * ASTG2)          // 110592 B

__global__ __launch_bounds__(256, 2) void attn_mma(int tile_off) {
    extern __shared__ __align__(16) char sm[];
    const uint32_t s = smem_u32(sm);
    const int tid = threadIdx.x, lane = tid & 31, w = tid >> 5;
    const int bh = blockIdx.y;
    const int q0 = (tile_off - (int)blockIdx.x) * 128;

    const __half* __restrict__ Qb = g_qh + (size_t)bh * S_ * HD_;
    const __half* __restrict__ Kb = g_kh + (size_t)bh * S_ * HD_;
    const __half* __restrict__ Vb = g_vh + (size_t)bh * S_ * HD_;

    const int r0 = q0 + w * 16 + (lane >> 2);
    const int cq = lane & 3;
    const float SC = 0.18033688f;                 // 0.125 * log2(e)
    uint32_t qf[4][4];
    {
        const __half2 sc2 = __floats2half2_rn(SC, SC);
        const __half2* Qr0 = (const __half2*)(Qb + (size_t)r0 * HD_);
        const __half2* Qr1 = (const __half2*)(Qb + (size_t)(r0 + 8) * HD_);
        #pragma unroll
        for (int t = 0; t < 4; ++t) {
            __half2 v0 = __hmul2(Qr0[t * 8 + cq], sc2);
            __half2 v1 = __hmul2(Qr1[t * 8 + cq], sc2);
            __half2 v2 = __hmul2(Qr0[t * 8 + 4 + cq], sc2);
            __half2 v3 = __hmul2(Qr1[t * 8 + 4 + cq], sc2);
            qf[t][0] = *(const uint32_t*)&v0;
            qf[t][1] = *(const uint32_t*)&v1;
            qf[t][2] = *(const uint32_t*)&v2;
            qf[t][3] = *(const uint32_t*)&v3;
        }
    }

    float o[8][4];
    #pragma unroll
    for (int j = 0; j < 8; ++j)
        #pragma unroll
        for (int x = 0; x < 4; ++x) o[j][x] = 0.f;
    float m0 = -INFINITY, m1 = -INFINITY, l0 = 0.f, l1 = 0.f;

    const int NT = (q0 + 128) / 128;              // 128-key tiles

    auto load_tile = [&](int kt, int stg) {
        const uint32_t base = s + stg * ASTG2;
        #pragma unroll
        for (int i = 0; i < 4; ++i) {
            int idx = tid + i * 256;              // 0..1023
            int row = idx >> 3, c = idx & 7;      // 128 rows x 8 chunks
            const size_t go = (size_t)(kt * 128 + row) * HD_ + c * 8;
            cpa16(base + row * ARS + c * 16, Kb + go);
            cpa16(base + ATILE2 + row * ARS + c * 16, Vb + go);
        }
    };

    load_tile(0, 0); cpa_commit();
    if (NT > 1) { load_tile(1, 1); cpa_commit(); }

    const int g = lane >> 3, lr = lane & 7;
    const uint32_t ONES2 = 0x3C003C00u;
    uint32_t onesb[2] = {ONES2, ONES2};

    #pragma unroll 1
    for (int kt = 0; kt < NT; ++kt) {
        if (kt < NT - 1) asm volatile("cp.async.wait_group 1;" ::: "memory");
        else             asm volatile("cp.async.wait_group 0;" ::: "memory");
        __syncthreads();
        if (kt + 2 < NT) { load_tile(kt + 2, (kt + 2) % 3); cpa_commit(); }

        const uint32_t sKbase = s + (kt % 3) * ASTG2;

        #pragma unroll 1
        for (int half64 = 0; half64 < 2; ++half64) {
            const int k0 = kt * 128 + half64 * 64;
            // warp-uniform skip of fully-masked chunks
            if (k0 > r0 + 8) break;
            const uint32_t sK = sKbase + half64 * 64 * ARS;
            const uint32_t sV = sKbase + ATILE2 + half64 * 64 * ARS;

            // ---- S = (Q*sc) K^T ----
            float sa[8][4];
            #pragma unroll
            for (int j = 0; j < 8; ++j)
                #pragma unroll
                for (int x = 0; x < 4; ++x) sa[j][x] = 0.f;
            #pragma unroll
            for (int t = 0; t < 4; ++t) {
                uint32_t kb[8][2];
                #pragma unroll
                for (int jp = 0; jp < 4; ++jp) {
                    const int n = jp * 16 + (g >> 1) * 8 + lr;
                    uint32_t addr = sK + n * ARS + t * 32 + (g & 1) * 16;
                    uint32_t r0_, r1_, r2_, r3_;
                    asm volatile("ldmatrix.sync.aligned.m8n8.x4.shared.b16 {%0,%1,%2,%3}, [%4];"
                                 : "=r"(r0_), "=r"(r1_), "=r"(r2_), "=r"(r3_) : "r"(addr));
                    kb[jp * 2][0] = r0_; kb[jp * 2][1] = r1_;
                    kb[jp * 2 + 1][0] = r2_; kb[jp * 2 + 1][1] = r3_;
                }
                #pragma unroll
                for (int j = 0; j < 8; ++j)
                    mma16816(sa[j], qf[t], kb[j]);
            }

            // ---- mask + running-max ----
            const bool needmask = (k0 + 63 > r0);
            float tm0 = -INFINITY, tm1 = -INFINITY;
            #pragma unroll
            for (int j = 0; j < 8; ++j) {
                if (needmask) {
                    const int col = k0 + j * 8 + (lane & 3) * 2;
                    if (col > r0)         sa[j][0] = -INFINITY;
                    if (col + 1 > r0)     sa[j][1] = -INFINITY;
                    if (col > r0 + 8)     sa[j][2] = -INFINITY;
                    if (col + 1 > r0 + 8) sa[j][3] = -INFINITY;
                }
                tm0 = fmaxf(tm0, fmaxf(sa[j][0], sa[j][1]));
                tm1 = fmaxf(tm1, fmaxf(sa[j][2], sa[j][3]));
            }
            tm0 = fmaxf(tm0, __shfl_xor_sync(0xffffffffu, tm0, 1));
            tm0 = fmaxf(tm0, __shfl_xor_sync(0xffffffffu, tm0, 2));
            tm1 = fmaxf(tm1, __shfl_xor_sync(0xffffffffu, tm1, 1));
            tm1 = fmaxf(tm1, __shfl_xor_sync(0xffffffffu, tm1, 2));

            const float mn0 = fmaxf(m0, tm0), mn1 = fmaxf(m1, tm1);
            const float c0 = ex2(m0 - mn0), c1 = ex2(m1 - mn1);
            m0 = mn0; m1 = mn1;

            // ---- P = exp2(S - m) in fp16x2 ----
            uint32_t pa[4][4];
            #pragma unroll
            for (int j = 0; j < 8; ++j) {
                const float a0 = sa[j][0] - mn0, a1 = sa[j][1] - mn0;
                const float a2 = sa[j][2] - mn1, a3 = sa[j][3] - mn1;
                uint32_t h01, h23;
                asm("cvt.rn.f16x2.f32 %0, %1, %2;" : "=r"(h01) : "f"(a1), "f"(a0));
                asm("cvt.rn.f16x2.f32 %0, %1, %2;" : "=r"(h23) : "f"(a3), "f"(a2));
                asm("ex2.approx.f16x2 %0, %1;" : "=r"(h01) : "r"(h01));
                asm("ex2.approx.f16x2 %0, %1;" : "=r"(h23) : "r"(h23));
                const int t = j >> 1;
                if ((j & 1) == 0) { pa[t][0] = h01; pa[t][1] = h23; }
                else              { pa[t][2] = h01; pa[t][3] = h23; }
            }

            // ---- rescale O ----
            #pragma unroll
            for (int j = 0; j < 8; ++j) {
                o[j][0] *= c0; o[j][1] *= c0;
                o[j][2] *= c1; o[j][3] *= c1;
            }

            // ---- O += P V, row sums via MMA ----
            float ls[4] = {0.f, 0.f, 0.f, 0.f};
            #pragma unroll
            for (int t = 0; t < 4; ++t) {
                uint32_t vb[8][2];
                #pragma unroll
                for (int jp = 0; jp < 4; ++jp) {
                    const int row = t * 16 + (g & 1) * 8 + lr;
                    uint32_t addr = sV + row * ARS + jp * 32 + (g >> 1) * 16;
                    uint32_t r0_, r1_, r2_, r3_;
                    asm volatile("ldmatrix.sync.aligned.m8n8.x4.trans.shared.b16 {%0,%1,%2,%3}, [%4];"
                                 : "=r"(r0_), "=r"(r1_), "=r"(r2_), "=r"(r3_) : "r"(addr));
                    vb[jp * 2][0] = r0_; vb[jp * 2][1] = r1_;
                    vb[jp * 2 + 1][0] = r2_; vb[jp * 2 + 1][1] = r3_;
                }
                mma16816(ls, pa[t], onesb);
                #pragma unroll
                for (int j = 0; j < 8; ++j)
                    mma16816(o[j], pa[t], vb[j]);
            }

            l0 = l0 * c0 + ls[0];
            l1 = l1 * c1 + ls[2];
        }
    }

    // ---- epilogue ----
    const float i0 = 1.f / l0, i1 = 1.f / l1;
    const int b = bh >> 4, h = bh & 15;
    __half* out0 = g_wvh + ((size_t)(b * S_) + r0) * D_ + h * HD_ + (lane & 3) * 2;
    __half* out1 = g_wvh + ((size_t)(b * S_) + r0 + 8) * D_ + h * HD_ + (lane & 3) * 2;
    #pragma unroll
    for (int j = 0; j < 8; ++j) {
        *(__half2*)(out0 + j * 8) = __floats2half2_rn(o[j][0] * i0, o[j][1] * i0);
        *(__half2*)(out1 + j * 8) = __floats2half2_rn(o[j][2] * i1, o[j][3] * i1);
    }
}

// ---------------------------------------------------------------------------
// fused prep (R13 layout)
// ---------------------------------------------------------------------------
#define NB_X  4096
#define NB_WO 512
#define NB_WT 3072

__global__ __launch_bounds__(512) void prep(
    const float* __restrict__ X,  const float* __restrict__ Wo,
    const float* __restrict__ Wq, const float* __restrict__ Wk,
    const float* __restrict__ Wv) {
    __shared__ float t[32][33];
    const int b = blockIdx.x, tid = threadIdx.x;

    if (b < NB_X) {
        const int i = (b * 512 + tid) * 4;
        float4 v = *(const float4*)(X + i);
        __half2* o = (__half2*)(g_xh + i);
        o[0] = __floats2half2_rn(v.x, v.y);
        o[1] = __floats2half2_rn(v.z, v.w);
    } else if (b < NB_X + NB_WO) {
        const int i = ((b - NB_X) * 512 + tid) * 4;
        float4 v = *(const float4*)(Wo + i);
        __half2* o = (__half2*)(g_woh + i);
        o[0] = __floats2half2_rn(v.x, v.y);
        o[1] = __floats2half2_rn(v.z, v.w);
    } else {
        if (tid >= 256) return;
        const int id = b - NB_X - NB_WO;
        const int bx = id & 1, by = (id >> 1) & 31, bz = id >> 6;
        const int z = bz >> 4, h = bz & 15;
        const float* W = ((z == 0) ? Wq : (z == 1) ? Wk : Wv) + (size_t)h * D_ * HD_;
        __half* out = g_wt + (size_t)bz * HD_ * D_;
        const int n0 = bx * 32, k0 = by * 32;
        const int tx = tid & 31, ty = tid >> 5;
        #pragma unroll
        for (int i = 0; i < 32; i += 8)
            t[ty + i][tx] = W[(size_t)(k0 + ty + i) * HD_ + n0 + tx];
        __syncthreads();
        #pragma unroll
        for (int i = 0; i < 32; i += 8)
            out[(size_t)(n0 + ty + i) * D_ + k0 + tx] = __float2half_rn(t[tx][ty + i]);
    }
}

// ---------------------------------------------------------------------------
extern "C" void kernel_launch(void* const* d_in, const int* in_sizes, int n_in,
                              void* d_out, int out_size) {
    const float* X  = (const float*)d_in[0];
    const float* Wq = (const float*)d_in[1];
    const float* bq = (const float*)d_in[2];
    const float* Wk = (const float*)d_in[3];
    const float* bk = (const float*)d_in[4];
    const float* Wv = (const float*)d_in[5];
    const float* bv = (const float*)d_in[6];
    const float* Wo = (const float*)d_in[7];
    const float* bo = (const float*)d_in[8];
    float* out = (float*)d_out;

    cudaFuncSetAttribute(qkv_mma, cudaFuncAttributeMaxDynamicSharedMemorySize, GSMEM);
    cudaFuncSetAttribute(out_mma, cudaFuncAttributeMaxDynamicSharedMemorySize, GSMEM);
    cudaFuncSetAttribute(attn_mma, cudaFuncAttributeMaxDynamicSharedMemorySize, ASMEM);

    __half* xh  = nullptr; cudaGetSymbolAddress((void**)&xh,  g_xh);
    __half* wvh = nullptr; cudaGetSymbolAddress((void**)&wvh, g_wvh);
    __half* wt  = nullptr; cudaGetSymbolAddress((void**)&wt,  g_wt);
    __half* woh = nullptr; cudaGetSymbolAddress((void**)&woh, g_woh);

    // side stream + fork/join events (host-side objects only; created on the
    // two host invocations of kernel_launch — correctness run and capture run)
    cudaStream_t s1;
    cudaEvent_t evQ, evL;
    cudaStreamCreateWithFlags(&s1, cudaStreamNonBlocking);
    cudaEventCreateWithFlags(&evQ, cudaEventDisableTiming);
    cudaEventCreateWithFlags(&evL, cudaEventDisableTiming);

    // stream 0 (captured): prep -> qkv
    prep<<<NB_X + NB_WO + NB_WT, 512>>>(X, Wo, Wq, Wk, Wv);
    qkv_mma<<<dim3(H_ / 2, M_ / 128, 3), 256, GSMEM>>>(xh, wt, bq, bk, bv);
    cudaEventRecord(evQ, 0);

    // stream 1: light half (q/s < 1024) -> attn_light, out_light
    cudaStreamWaitEvent(s1, evQ, 0);
    attn_mma<<<dim3(8, B_ * H_), 256, ASMEM, s1>>>(7);
    out_mma<<<dim3(8, 32), 256, GSMEM, s1>>>(wvh, woh, bo, out, 0);
    cudaEventRecord(evL, s1);

    // stream 0: heavy half (q/s >= 1024) -> attn_heavy, out_heavy; then join
    attn_mma<<<dim3(8, B_ * H_), 256, ASMEM>>>(15);
    out_mma<<<dim3(8, 32), 256, GSMEM>>>(wvh, woh, bo, out, 8);
    cudaStreamWaitEvent(0, evL, 0);
}